// round 2
// baseline (speedup 1.0000x reference)
#include <cuda_runtime.h>
#include <cstdint>

#define BB 2
#define NNx 768
#define DDx 512
#define HHx 16
#define DHx 32
#define INNERx 512
#define PDx 128
#define NEG_INFx -10000.0f
#define LN_EPS 1e-5f

// ---------------- scratch (static device memory: allowed) ----------------
__device__ float g_x[BB * NNx * DDx];                      // LN(node)          3 MB
__device__ float g_qkvg[BB * NNx * 2048];                  // [q|k|v|g]        12.6 MB
__device__ float g_qh[BB * HHx * NNx * DHx];               // q head-major      3 MB
__device__ float g_kh[BB * HHx * NNx * DHx];
__device__ float g_vh[BB * HHx * NNx * DHx];
__device__ float g_bias[(size_t)BB * HHx * NNx * NNx];     // masked bias     75.5 MB
__device__ float g_og[BB * NNx * INNERx];                  // gated attn out    3 MB
__device__ float g_Wt[HHx * 132];                          // W' transposed, padded
__device__ float g_sh[HHx];                                // sum_e W'_eh
__device__ float g_th[HHx];                                // sum_e b_e W_eh

// ---------------- K0: fold pair-LN affine into projection weights ----------------
__global__ void k_prep(const float* __restrict__ bias_w,
                       const float* __restrict__ pnw,
                       const float* __restrict__ pnb) {
    int t = threadIdx.x;
    for (int idx = t; idx < PDx * HHx; idx += blockDim.x) {
        int e = idx >> 4, h = idx & 15;
        g_Wt[h * 132 + e] = pnw[e] * bias_w[idx];
    }
    if (t < HHx) {
        float s = 0.f, tt = 0.f;
        for (int e = 0; e < PDx; e++) {
            s  += pnw[e] * bias_w[e * HHx + t];
            tt += pnb[e] * bias_w[e * HHx + t];
        }
        g_sh[t] = s;
        g_th[t] = tt;
    }
}

// ---------------- K1: node LayerNorm ----------------
__global__ void k_ln_node(const float* __restrict__ nf,
                          const float* __restrict__ w,
                          const float* __restrict__ bp) {
    int row = blockIdx.x;
    const float* in = nf + (size_t)row * DDx;
    float s = 0.f, ss = 0.f;
    for (int c = threadIdx.x; c < DDx; c += 256) {
        float t = in[c];
        s += t; ss += t * t;
    }
#pragma unroll
    for (int o = 16; o > 0; o >>= 1) {
        s  += __shfl_xor_sync(~0u, s, o);
        ss += __shfl_xor_sync(~0u, ss, o);
    }
    __shared__ float red[16];
    int wid = threadIdx.x >> 5, lid = threadIdx.x & 31;
    if (lid == 0) { red[wid] = s; red[8 + wid] = ss; }
    __syncthreads();
    __shared__ float sm, sr;
    if (threadIdx.x == 0) {
        float S = 0.f, SS = 0.f;
        for (int i = 0; i < 8; i++) { S += red[i]; SS += red[8 + i]; }
        float m = S / DDx;
        sm = m;
        sr = rsqrtf(SS / DDx - m * m + LN_EPS);
    }
    __syncthreads();
    float m = sm, r = sr;
    for (int c = threadIdx.x; c < DDx; c += 256)
        g_x[(size_t)row * DDx + c] = (in[c] - m) * r * w[c] + bp[c];
}

// ---------------- K2: fused QKV+G GEMM  x(1536x512) @ [Wqkv|Wg](512x2048) ----------------
__global__ void k_gemm_qkvg(const float* __restrict__ Wq, const float* __restrict__ bq,
                            const float* __restrict__ Wg, const float* __restrict__ bgp) {
    __shared__ __align__(16) float As[16][128];
    __shared__ __align__(16) float Bs[16][64];
    int bm = blockIdx.y * 128, bn = blockIdx.x * 64;
    int tid = threadIdx.x;
    int tr = tid >> 4, tc = tid & 15;
    float acc[8][4];
#pragma unroll
    for (int i = 0; i < 8; i++)
#pragma unroll
        for (int j = 0; j < 4; j++) acc[i][j] = 0.f;

    for (int k0 = 0; k0 < 512; k0 += 16) {
#pragma unroll
        for (int q = 0; q < 2; q++) {
            int f = tid * 2 + q;
            int r = f >> 2, c4 = (f & 3) << 2;
            float4 a = *(const float4*)&g_x[(size_t)(bm + r) * 512 + k0 + c4];
            As[c4 + 0][r] = a.x; As[c4 + 1][r] = a.y;
            As[c4 + 2][r] = a.z; As[c4 + 3][r] = a.w;
        }
        {
            int r = tid >> 4, c = (tid & 15) << 2;
            int n = bn + c;
            float4 bv;
            if (n < 1536) bv = *(const float4*)&Wq[(size_t)(k0 + r) * 1536 + n];
            else          bv = *(const float4*)&Wg[(size_t)(k0 + r) * 512 + (n - 1536)];
            *(float4*)&Bs[r][c] = bv;
        }
        __syncthreads();
#pragma unroll
        for (int kk = 0; kk < 16; kk++) {
            float4 a0 = *(const float4*)&As[kk][tr * 8];
            float4 a1 = *(const float4*)&As[kk][tr * 8 + 4];
            float4 b0 = *(const float4*)&Bs[kk][tc * 4];
            float av[8] = {a0.x, a0.y, a0.z, a0.w, a1.x, a1.y, a1.z, a1.w};
            float bv[4] = {b0.x, b0.y, b0.z, b0.w};
#pragma unroll
            for (int i = 0; i < 8; i++)
#pragma unroll
                for (int j = 0; j < 4; j++) acc[i][j] += av[i] * bv[j];
        }
        __syncthreads();
    }
#pragma unroll
    for (int i = 0; i < 8; i++) {
        int row = bm + tr * 8 + i;
#pragma unroll
        for (int j = 0; j < 4; j++) {
            int col = bn + tc * 4 + j;
            float bias = (col < 1536) ? bq[col] : bgp[col - 1536];
            g_qkvg[(size_t)row * 2048 + col] = acc[i][j] + bias;
        }
    }
}

// ---------------- K3: q/k LN over INNER + transpose q,k,v to head-major ----------------
__global__ void k_lnqk(const float* __restrict__ qw, const float* __restrict__ qb,
                       const float* __restrict__ kw, const float* __restrict__ kb) {
    int bn = blockIdx.x;
    const float* row = g_qkvg + (size_t)bn * 2048;
    int b = bn / NNx, nn = bn % NNx;
    float s1 = 0.f, ss1 = 0.f, s2 = 0.f, ss2 = 0.f;
    for (int c = threadIdx.x; c < 512; c += 256) {
        float a = row[c], b2 = row[512 + c];
        s1 += a; ss1 += a * a; s2 += b2; ss2 += b2 * b2;
    }
#pragma unroll
    for (int o = 16; o > 0; o >>= 1) {
        s1  += __shfl_xor_sync(~0u, s1, o);  ss1 += __shfl_xor_sync(~0u, ss1, o);
        s2  += __shfl_xor_sync(~0u, s2, o);  ss2 += __shfl_xor_sync(~0u, ss2, o);
    }
    __shared__ float red[4][8];
    int w = threadIdx.x >> 5, lane = threadIdx.x & 31;
    if (lane == 0) { red[0][w] = s1; red[1][w] = ss1; red[2][w] = s2; red[3][w] = ss2; }
    __syncthreads();
    __shared__ float st[4];
    if (threadIdx.x == 0) {
        float a = 0.f, bb = 0.f, c = 0.f, d = 0.f;
        for (int i = 0; i < 8; i++) { a += red[0][i]; bb += red[1][i]; c += red[2][i]; d += red[3][i]; }
        float m1 = a / 512.f, m2 = c / 512.f;
        st[0] = m1; st[1] = rsqrtf(bb / 512.f - m1 * m1 + LN_EPS);
        st[2] = m2; st[3] = rsqrtf(d / 512.f - m2 * m2 + LN_EPS);
    }
    __syncthreads();
    float m1 = st[0], r1 = st[1], m2 = st[2], r2 = st[3];
    for (int c = threadIdx.x; c < 512; c += 256) {
        int h = c >> 5, d = c & 31;
        size_t oidx = (((size_t)(b * HHx + h)) * NNx + nn) * DHx + d;
        g_qh[oidx] = (row[c]       - m1) * r1 * qw[c] + qb[c];
        g_kh[oidx] = (row[512 + c] - m2) * r2 * kw[c] + kb[c];
        g_vh[oidx] = row[1024 + c];
    }
}

// ---------------- K4: pair bias (LN folded) + mask, output [b][h][i][j] ----------------
// mask arrives as 4-byte elements (bool widened by the harness to int32/float32);
// nonzero bit-pattern == true for both.
__global__ void k_pairbias(const float* __restrict__ pair, const int* __restrict__ mask) {
    __shared__ __align__(16) float Wts[HHx * 132];
    __shared__ __align__(16) float sp[8][PDx];
    __shared__ float outT[HHx][33];
    __shared__ float ssh[HHx], sth[HHx];
    int tid = threadIdx.x, w = tid >> 5, lane = tid & 31;
    for (int c = tid; c < HHx * 132; c += 256) Wts[c] = g_Wt[c];
    if (tid < HHx) { ssh[tid] = g_sh[tid]; sth[tid] = g_th[tid]; }
    __syncthreads();

    int j0 = blockIdx.x * 32;
    int i = blockIdx.y, b = blockIdx.z;
    size_t rowbase = ((size_t)(b * NNx + i)) * NNx;
    int hm = lane & 15, half = lane >> 4;

    for (int rr = 0; rr < 4; rr++) {
        int j = j0 + w * 4 + rr;
        const float* pr = pair + (rowbase + j) * (size_t)PDx;
        float4 pv = *(const float4*)&pr[lane * 4];
        *(float4*)&sp[w][lane * 4] = pv;
        float s  = pv.x + pv.y + pv.z + pv.w;
        float ss = pv.x * pv.x + pv.y * pv.y + pv.z * pv.z + pv.w * pv.w;
#pragma unroll
        for (int o = 16; o > 0; o >>= 1) {
            s  += __shfl_xor_sync(~0u, s, o);
            ss += __shfl_xor_sync(~0u, ss, o);
        }
        float m    = s * (1.0f / PDx);
        float var  = ss * (1.0f / PDx) - m * m;
        float rstd = rsqrtf(var + LN_EPS);
        __syncwarp();
        float acc = 0.f;
#pragma unroll
        for (int c = 0; c < 16; c++) {
            int e = half * 64 + c * 4;
            float4 p4 = *(const float4*)&sp[w][e];
            float4 w4 = *(const float4*)&Wts[hm * 132 + e];
            acc += p4.x * w4.x + p4.y * w4.y + p4.z * w4.z + p4.w * w4.w;
        }
        acc += __shfl_xor_sync(~0u, acc, 16);
        if (lane < 16) {
            float bv = rstd * acc - rstd * m * ssh[hm] + sth[hm];
            if (mask[rowbase + j] == 0) bv = NEG_INFx;
            outT[hm][w * 4 + rr] = bv;
        }
        __syncwarp();
    }
    __syncthreads();
    for (int idx = tid; idx < HHx * 32; idx += 256) {
        int h = idx >> 5, jj = idx & 31;
        g_bias[(((size_t)(b * HHx + h)) * NNx + i) * NNx + j0 + jj] = outT[h][jj];
    }
}

// ---------------- K5: attention (one warp per query row) + sigmoid gating ----------------
__global__ void k_attn() {
    __shared__ __align__(16) float S[8][NNx];
    __shared__ __align__(16) float qs[8][DHx];
    int i0 = blockIdx.x * 8;
    int h = blockIdx.y, b = blockIdx.z;
    int tid = threadIdx.x;
    int w = tid >> 5, lane = tid & 31;
    size_t bhbase = (size_t)(b * HHx + h) * NNx;

    {
        int ii = tid >> 5, d = tid & 31;
        qs[ii][d] = g_qh[(bhbase + i0 + ii) * DHx + d];
    }
    __syncthreads();

    const float scale = 0.17677669529663687f;   // 1/sqrt(32)
    int i = i0 + w;
    const float* biasrow = g_bias + (bhbase + i) * NNx;

    for (int jt = 0; jt < NNx / 32; jt++) {
        int j = jt * 32 + lane;
        const float* kr = g_kh + (bhbase + j) * DHx;
        float acc = 0.f;
#pragma unroll
        for (int d4 = 0; d4 < 8; d4++) {
            float4 kv = *(const float4*)&kr[d4 * 4];
            float4 qv = *(const float4*)&qs[w][d4 * 4];
            acc += kv.x * qv.x + kv.y * qv.y + kv.z * qv.z + kv.w * qv.w;
        }
        S[w][j] = acc * scale + biasrow[j];
    }
    __syncwarp();

    float mx = -3.4e38f;
    for (int c = lane; c < NNx; c += 32) mx = fmaxf(mx, S[w][c]);
#pragma unroll
    for (int o = 16; o > 0; o >>= 1) mx = fmaxf(mx, __shfl_xor_sync(~0u, mx, o));
    float sum = 0.f;
    for (int c = lane; c < NNx; c += 32) {
        float e = __expf(S[w][c] - mx);
        S[w][c] = e;
        sum += e;
    }
#pragma unroll
    for (int o = 16; o > 0; o >>= 1) sum += __shfl_xor_sync(~0u, sum, o);
    float inv = 1.0f / sum;
    __syncwarp();

    float acc = 0.f;
    const float* vb = g_vh + bhbase * DHx;
    for (int j = 0; j < NNx; j += 4) {
        float p0 = S[w][j], p1 = S[w][j + 1], p2 = S[w][j + 2], p3 = S[w][j + 3];
        acc += p0 * vb[(size_t)(j    ) * DHx + lane];
        acc += p1 * vb[(size_t)(j + 1) * DHx + lane];
        acc += p2 * vb[(size_t)(j + 2) * DHx + lane];
        acc += p3 * vb[(size_t)(j + 3) * DHx + lane];
    }
    acc *= inv;

    size_t bn = (size_t)b * NNx + i;
    float g  = g_qkvg[bn * 2048 + 1536 + h * DHx + lane];
    float sg = 1.0f / (1.0f + __expf(-g));
    g_og[bn * INNERx + h * DHx + lane] = acc * sg;
}

// ---------------- K6: output GEMM  o(1536x512) @ out_w(512x512) + out_b ----------------
__global__ void k_gemm_out(const float* __restrict__ W, const float* __restrict__ bo,
                           float* __restrict__ C) {
    __shared__ __align__(16) float As[16][128];
    __shared__ __align__(16) float Bs[16][64];
    int bm = blockIdx.y * 128, bn = blockIdx.x * 64;
    int tid = threadIdx.x;
    int tr = tid >> 4, tc = tid & 15;
    float acc[8][4];
#pragma unroll
    for (int i = 0; i < 8; i++)
#pragma unroll
        for (int j = 0; j < 4; j++) acc[i][j] = 0.f;

    for (int k0 = 0; k0 < 512; k0 += 16) {
#pragma unroll
        for (int q = 0; q < 2; q++) {
            int f = tid * 2 + q;
            int r = f >> 2, c4 = (f & 3) << 2;
            float4 a = *(const float4*)&g_og[(size_t)(bm + r) * 512 + k0 + c4];
            As[c4 + 0][r] = a.x; As[c4 + 1][r] = a.y;
            As[c4 + 2][r] = a.z; As[c4 + 3][r] = a.w;
        }
        {
            int r = tid >> 4, c = (tid & 15) << 2;
            float4 bv = *(const float4*)&W[(size_t)(k0 + r) * 512 + bn + c];
            *(float4*)&Bs[r][c] = bv;
        }
        __syncthreads();
#pragma unroll
        for (int kk = 0; kk < 16; kk++) {
            float4 a0 = *(const float4*)&As[kk][tr * 8];
            float4 a1 = *(const float4*)&As[kk][tr * 8 + 4];
            float4 b0 = *(const float4*)&Bs[kk][tc * 4];
            float av[8] = {a0.x, a0.y, a0.z, a0.w, a1.x, a1.y, a1.z, a1.w};
            float bv[4] = {b0.x, b0.y, b0.z, b0.w};
#pragma unroll
            for (int i = 0; i < 8; i++)
#pragma unroll
                for (int j = 0; j < 4; j++) acc[i][j] += av[i] * bv[j];
        }
        __syncthreads();
    }
#pragma unroll
    for (int i = 0; i < 8; i++) {
        int row = bm + tr * 8 + i;
#pragma unroll
        for (int j = 0; j < 4; j++) {
            int col = bn + tc * 4 + j;
            C[(size_t)row * 512 + col] = acc[i][j] + bo[col];
        }
    }
}

// ---------------- launch ----------------
extern "C" void kernel_launch(void* const* d_in, const int* in_sizes, int n_in,
                              void* d_out, int out_size) {
    const float* node = (const float*)d_in[0];
    const float* pair = (const float*)d_in[1];
    const int*   mask = (const int*)d_in[2];
    const float* nnw  = (const float*)d_in[3];
    const float* nnb  = (const float*)d_in[4];
    const float* qkvw = (const float*)d_in[5];
    const float* qkvb = (const float*)d_in[6];
    const float* gw   = (const float*)d_in[7];
    const float* gb   = (const float*)d_in[8];
    const float* qlw  = (const float*)d_in[9];
    const float* qlb  = (const float*)d_in[10];
    const float* klw  = (const float*)d_in[11];
    const float* klb  = (const float*)d_in[12];
    const float* pnw  = (const float*)d_in[13];
    const float* pnb  = (const float*)d_in[14];
    const float* bw   = (const float*)d_in[15];
    const float* ow   = (const float*)d_in[16];
    const float* ob   = (const float*)d_in[17];
    float* out = (float*)d_out;

    k_prep<<<1, 256>>>(bw, pnw, pnb);
    k_ln_node<<<BB * NNx, 256>>>(node, nnw, nnb);
    k_gemm_qkvg<<<dim3(2048 / 64, (BB * NNx) / 128), 256>>>(qkvw, qkvb, gw, gb);
    k_lnqk<<<BB * NNx, 256>>>(qlw, qlb, klw, klb);
    k_pairbias<<<dim3(NNx / 32, NNx, BB), 256>>>(pair, mask);
    k_attn<<<dim3(NNx / 8, HHx, BB), 256>>>();
    k_gemm_out<<<dim3(512 / 64, (BB * NNx) / 128), 256>>>(ow, ob, out);
}

// round 3
// speedup vs baseline: 1.5143x; 1.5143x over previous
#include <cuda_runtime.h>
#include <cstdint>

#define BB 2
#define NNx 768
#define DDx 512
#define HHx 16
#define DHx 32
#define INNERx 512
#define PDx 128
#define NEG_INFx -10000.0f
#define LN_EPS 1e-5f

typedef unsigned long long u64;

// ---------------- f32x2 packed-math helpers (exact fp32 semantics) ----------------
__device__ __forceinline__ void ffma2(u64& d, u64 a, u64 b) {
    asm("fma.rn.f32x2 %0, %1, %2, %0;" : "+l"(d) : "l"(a), "l"(b));
}
__device__ __forceinline__ void fadd2(u64& d, u64 a) {
    asm("add.rn.f32x2 %0, %1, %0;" : "+l"(d) : "l"(a));
}
__device__ __forceinline__ float2 up2(u64 v) {
    float2 f;
    asm("mov.b64 {%0, %1}, %2;" : "=f"(f.x), "=f"(f.y) : "l"(v));
    return f;
}
__device__ __forceinline__ float hadd2(u64 v) {
    float2 f = up2(v);
    return f.x + f.y;
}
__device__ __forceinline__ u64 splat2(float x) {
    u64 r;
    asm("mov.b64 %0, {%1, %1};" : "=l"(r) : "f"(x));
    return r;
}

// ---------------- scratch (static device memory: allowed) ----------------
__device__ float g_x[BB * NNx * DDx];
__device__ float g_qkvg[BB * NNx * 2048];                  // [q|k|v|g]
__device__ float g_qh[BB * HHx * NNx * DHx];
__device__ float g_kh[BB * HHx * NNx * DHx];
__device__ float g_vh[BB * HHx * NNx * DHx];
__device__ float g_bias[(size_t)BB * HHx * NNx * NNx];     // masked bias  75.5 MB
__device__ float g_og[BB * NNx * INNERx];
__device__ float g_Wt[HHx * PDx];                          // W'[h][e] = pnw[e]*bias_w[e][h]
__device__ float g_sh[HHx];
__device__ float g_th[HHx];

// ---------------- K0: fold pair-LN affine into projection weights ----------------
__global__ void k_prep(const float* __restrict__ bias_w,
                       const float* __restrict__ pnw,
                       const float* __restrict__ pnb) {
    int t = threadIdx.x;
    for (int idx = t; idx < HHx * PDx; idx += blockDim.x) {
        int h = idx >> 7, e = idx & 127;
        g_Wt[idx] = pnw[e] * bias_w[e * HHx + h];
    }
    if (t < HHx) {
        float s = 0.f, tt = 0.f;
        for (int e = 0; e < PDx; e++) {
            s  += pnw[e] * bias_w[e * HHx + t];
            tt += pnb[e] * bias_w[e * HHx + t];
        }
        g_sh[t] = s;
        g_th[t] = tt;
    }
}

// ---------------- K1: node LayerNorm ----------------
__global__ void k_ln_node(const float* __restrict__ nf,
                          const float* __restrict__ w,
                          const float* __restrict__ bp) {
    int row = blockIdx.x;
    const float* in = nf + (size_t)row * DDx;
    float s = 0.f, ss = 0.f;
    for (int c = threadIdx.x; c < DDx; c += 256) {
        float t = in[c];
        s += t; ss += t * t;
    }
#pragma unroll
    for (int o = 16; o > 0; o >>= 1) {
        s  += __shfl_xor_sync(~0u, s, o);
        ss += __shfl_xor_sync(~0u, ss, o);
    }
    __shared__ float red[16];
    int wid = threadIdx.x >> 5, lid = threadIdx.x & 31;
    if (lid == 0) { red[wid] = s; red[8 + wid] = ss; }
    __syncthreads();
    __shared__ float sm, sr;
    if (threadIdx.x == 0) {
        float S = 0.f, SS = 0.f;
        for (int i = 0; i < 8; i++) { S += red[i]; SS += red[8 + i]; }
        float m = S / DDx;
        sm = m;
        sr = rsqrtf(SS / DDx - m * m + LN_EPS);
    }
    __syncthreads();
    float m = sm, r = sr;
    for (int c = threadIdx.x; c < DDx; c += 256)
        g_x[(size_t)row * DDx + c] = (in[c] - m) * r * w[c] + bp[c];
}

// ---------------- K2: fused QKV+G GEMM (f32x2, i-pair packed) ----------------
__global__ void k_gemm_qkvg(const float* __restrict__ Wq, const float* __restrict__ bq,
                            const float* __restrict__ Wg, const float* __restrict__ bgp) {
    __shared__ __align__(16) float As[16][128];
    __shared__ __align__(16) float Bs[16][64];
    int bm = blockIdx.y * 128, bn = blockIdx.x * 64;
    int tid = threadIdx.x;
    int tr = tid >> 4, tc = tid & 15;
    u64 acc[4][4];   // [i-pair][j]
#pragma unroll
    for (int i = 0; i < 4; i++)
#pragma unroll
        for (int j = 0; j < 4; j++) acc[i][j] = 0ull;

    for (int k0 = 0; k0 < 512; k0 += 16) {
#pragma unroll
        for (int q = 0; q < 2; q++) {
            int f = tid * 2 + q;
            int r = f >> 2, c4 = (f & 3) << 2;
            float4 a = *(const float4*)&g_x[(size_t)(bm + r) * 512 + k0 + c4];
            As[c4 + 0][r] = a.x; As[c4 + 1][r] = a.y;
            As[c4 + 2][r] = a.z; As[c4 + 3][r] = a.w;
        }
        {
            int r = tid >> 4, c = (tid & 15) << 2;
            int n = bn + c;
            float4 bv;
            if (n < 1536) bv = *(const float4*)&Wq[(size_t)(k0 + r) * 1536 + n];
            else          bv = *(const float4*)&Wg[(size_t)(k0 + r) * 512 + (n - 1536)];
            *(float4*)&Bs[r][c] = bv;
        }
        __syncthreads();
#pragma unroll
        for (int kk = 0; kk < 16; kk++) {
            ulonglong2 aLo = *(const ulonglong2*)&As[kk][tr * 8];       // pairs (r0,r1),(r2,r3)
            ulonglong2 aHi = *(const ulonglong2*)&As[kk][tr * 8 + 4];   // (r4,r5),(r6,r7)
            float4 b0 = *(const float4*)&Bs[kk][tc * 4];
            u64 s0 = splat2(b0.x), s1 = splat2(b0.y), s2 = splat2(b0.z), s3 = splat2(b0.w);
            ffma2(acc[0][0], aLo.x, s0); ffma2(acc[0][1], aLo.x, s1);
            ffma2(acc[0][2], aLo.x, s2); ffma2(acc[0][3], aLo.x, s3);
            ffma2(acc[1][0], aLo.y, s0); ffma2(acc[1][1], aLo.y, s1);
            ffma2(acc[1][2], aLo.y, s2); ffma2(acc[1][3], aLo.y, s3);
            ffma2(acc[2][0], aHi.x, s0); ffma2(acc[2][1], aHi.x, s1);
            ffma2(acc[2][2], aHi.x, s2); ffma2(acc[2][3], aHi.x, s3);
            ffma2(acc[3][0], aHi.y, s0); ffma2(acc[3][1], aHi.y, s1);
            ffma2(acc[3][2], aHi.y, s2); ffma2(acc[3][3], aHi.y, s3);
        }
        __syncthreads();
    }
#pragma unroll
    for (int ip = 0; ip < 4; ip++) {
        int r0 = bm + tr * 8 + ip * 2;
#pragma unroll
        for (int j = 0; j < 4; j++) {
            int col = bn + tc * 4 + j;
            float bias = (col < 1536) ? bq[col] : bgp[col - 1536];
            float2 v = up2(acc[ip][j]);
            g_qkvg[(size_t)r0 * 2048 + col]       = v.x + bias;
            g_qkvg[(size_t)(r0 + 1) * 2048 + col] = v.y + bias;
        }
    }
}

// ---------------- K3: q/k LN over INNER + transpose q,k,v to head-major ----------------
__global__ void k_lnqk(const float* __restrict__ qw, const float* __restrict__ qb,
                       const float* __restrict__ kw, const float* __restrict__ kb) {
    int bn = blockIdx.x;
    const float* row = g_qkvg + (size_t)bn * 2048;
    int b = bn / NNx, nn = bn % NNx;
    float s1 = 0.f, ss1 = 0.f, s2 = 0.f, ss2 = 0.f;
    for (int c = threadIdx.x; c < 512; c += 256) {
        float a = row[c], b2 = row[512 + c];
        s1 += a; ss1 += a * a; s2 += b2; ss2 += b2 * b2;
    }
#pragma unroll
    for (int o = 16; o > 0; o >>= 1) {
        s1  += __shfl_xor_sync(~0u, s1, o);  ss1 += __shfl_xor_sync(~0u, ss1, o);
        s2  += __shfl_xor_sync(~0u, s2, o);  ss2 += __shfl_xor_sync(~0u, ss2, o);
    }
    __shared__ float red[4][8];
    int w = threadIdx.x >> 5, lane = threadIdx.x & 31;
    if (lane == 0) { red[0][w] = s1; red[1][w] = ss1; red[2][w] = s2; red[3][w] = ss2; }
    __syncthreads();
    __shared__ float st[4];
    if (threadIdx.x == 0) {
        float a = 0.f, bb = 0.f, c = 0.f, d = 0.f;
        for (int i = 0; i < 8; i++) { a += red[0][i]; bb += red[1][i]; c += red[2][i]; d += red[3][i]; }
        float m1 = a / 512.f, m2 = c / 512.f;
        st[0] = m1; st[1] = rsqrtf(bb / 512.f - m1 * m1 + LN_EPS);
        st[2] = m2; st[3] = rsqrtf(d / 512.f - m2 * m2 + LN_EPS);
    }
    __syncthreads();
    float m1 = st[0], r1 = st[1], m2 = st[2], r2 = st[3];
    for (int c = threadIdx.x; c < 512; c += 256) {
        int h = c >> 5, d = c & 31;
        size_t oidx = (((size_t)(b * HHx + h)) * NNx + nn) * DHx + d;
        g_qh[oidx] = (row[c]       - m1) * r1 * qw[c] + qb[c];
        g_kh[oidx] = (row[512 + c] - m2) * r2 * kw[c] + kb[c];
        g_vh[oidx] = row[1024 + c];
    }
}

// ---------------- K4: pair bias mini-GEMM (LN folded, f32x2 e-pair packed) ----------------
// Block: 64 j-rows of one (b,i) x 16 h. Thread: 2 j x 2 h over K=128.
#define SP_STRIDE 136
#define WT_STRIDE 140
__global__ void k_pairbias(const float* __restrict__ pair, const int* __restrict__ mask) {
    __shared__ __align__(16) float sp[64 * SP_STRIDE];     // 34816 B
    __shared__ __align__(16) float Wts[HHx * WT_STRIDE];   //  8960 B
    __shared__ float outT[HHx * 64];                       //  4096 B
    __shared__ float smM[64], smR[64];
    __shared__ float sh_s[HHx], th_s[HHx];

    int tid = threadIdx.x;
    int j0 = blockIdx.x * 64;
    int i  = blockIdx.y, b = blockIdx.z;
    size_t rowbase = ((size_t)(b * NNx + i)) * NNx;

    // stage weights
    for (int idx = tid; idx < HHx * PDx; idx += 256) {
        int h = idx >> 7, e = idx & 127;
        Wts[h * WT_STRIDE + e] = g_Wt[idx];
    }
    if (tid < HHx) { sh_s[tid] = g_sh[tid]; th_s[tid] = g_th[tid]; }

    // stage 64x128 p-tile (coalesced float4)
    const float* pbase = pair + (rowbase + j0) * (size_t)PDx;
#pragma unroll
    for (int it = 0; it < 8; it++) {
        int f = tid + it * 256;          // float4 index, 0..2047
        int r = f >> 5, c4 = (f & 31) << 2;
        float4 v = *(const float4*)&pbase[(size_t)r * PDx + c4];
        *(float4*)&sp[r * SP_STRIDE + c4] = v;
    }
    __syncthreads();

    int jp = tid >> 3;        // 0..31  -> rows 2jp, 2jp+1
    int hp = tid & 7;         // h = hp, hp+8
    const float* spj0 = sp + (2 * jp) * SP_STRIDE;
    const float* spj1 = sp + (2 * jp + 1) * SP_STRIDE;
    const float* w0p  = Wts + hp * WT_STRIDE;
    const float* w1p  = Wts + (hp + 8) * WT_STRIDE;
    bool dosum = (hp == 0);

    u64 a00 = 0, a01 = 0, a10 = 0, a11 = 0;       // [j][hh]
    u64 s0 = 0, ss0 = 0, s1 = 0, ss1 = 0;

#pragma unroll 4
    for (int e = 0; e < PDx; e += 4) {
        ulonglong2 p0 = *(const ulonglong2*)(spj0 + e);
        ulonglong2 p1 = *(const ulonglong2*)(spj1 + e);
        ulonglong2 w0 = *(const ulonglong2*)(w0p + e);
        ulonglong2 w1 = *(const ulonglong2*)(w1p + e);
        ffma2(a00, p0.x, w0.x); ffma2(a00, p0.y, w0.y);
        ffma2(a01, p0.x, w1.x); ffma2(a01, p0.y, w1.y);
        ffma2(a10, p1.x, w0.x); ffma2(a10, p1.y, w0.y);
        ffma2(a11, p1.x, w1.x); ffma2(a11, p1.y, w1.y);
        if (dosum) {
            fadd2(s0, p0.x); fadd2(s0, p0.y); ffma2(ss0, p0.x, p0.x); ffma2(ss0, p0.y, p0.y);
            fadd2(s1, p1.x); fadd2(s1, p1.y); ffma2(ss1, p1.x, p1.x); ffma2(ss1, p1.y, p1.y);
        }
    }

    if (dosum) {
        float sA = hadd2(s0), qA = hadd2(ss0);
        float sB = hadd2(s1), qB = hadd2(ss1);
        float mA = sA * (1.0f / PDx), mB = sB * (1.0f / PDx);
        smM[2 * jp]     = mA;  smR[2 * jp]     = rsqrtf(qA * (1.0f / PDx) - mA * mA + LN_EPS);
        smM[2 * jp + 1] = mB;  smR[2 * jp + 1] = rsqrtf(qB * (1.0f / PDx) - mB * mB + LN_EPS);
    }
    __syncthreads();

    const int* maskrow = mask + rowbase + j0;
    float accf[2][2] = {{hadd2(a00), hadd2(a01)}, {hadd2(a10), hadd2(a11)}};
#pragma unroll
    for (int jj = 0; jj < 2; jj++) {
        int jl = 2 * jp + jj;
        float m = smM[jl], r = smR[jl];
        int msk = maskrow[jl];
#pragma unroll
        for (int hh = 0; hh < 2; hh++) {
            int h = hp + hh * 8;
            float bv = r * accf[jj][hh] - r * m * sh_s[h] + th_s[h];
            if (msk == 0) bv = NEG_INFx;
            outT[h * 64 + jl] = bv;
        }
    }
    __syncthreads();

    // coalesced write of [16][64] bias tile
    {
        int h = tid >> 4, c = (tid & 15) << 2;
        float4 v = *(const float4*)&outT[h * 64 + c];
        *(float4*)&g_bias[(((size_t)(b * HHx + h)) * NNx + i) * NNx + j0 + c] = v;
    }
}

// ---------------- K5: attention, 12 rows/block, warp owns 2 rows ----------------
__global__ void k_attn() {
    __shared__ __align__(16) float S[12][NNx];    // 36864 B
    __shared__ __align__(16) float qs[12][DHx];   //  1536 B
    int i0 = blockIdx.x * 12;
    int h = blockIdx.y, b = blockIdx.z;
    int tid = threadIdx.x;
    int w = tid >> 5, lane = tid & 31;
    size_t bhbase = (size_t)(b * HHx + h) * NNx;

    for (int idx = tid; idx < 12 * DHx; idx += 192) {
        int r = idx >> 5, d = idx & 31;
        qs[r][d] = g_qh[(bhbase + i0 + r) * DHx + d];
    }
    __syncthreads();

    const float scale = 0.17677669529663687f;   // 1/sqrt(32)
    int il0 = 2 * w, il1 = 2 * w + 1;
    int iA = i0 + il0, iB = i0 + il1;
    const float* b0row = g_bias + (bhbase + iA) * NNx;
    const float* b1row = g_bias + (bhbase + iB) * NNx;
    const float* q0p = &qs[il0][0];
    const float* q1p = &qs[il1][0];

    // QK^T for both rows per K-load (f32x2 packed over d)
    for (int jt = 0; jt < NNx / 32; jt++) {
        int j = jt * 32 + lane;
        const float* kr = g_kh + (bhbase + j) * DHx;
        u64 acc0 = 0, acc1 = 0;
#pragma unroll
        for (int d4 = 0; d4 < 8; d4++) {
            ulonglong2 kv = *(const ulonglong2*)(kr + d4 * 4);
            ulonglong2 q0 = *(const ulonglong2*)(q0p + d4 * 4);
            ulonglong2 q1 = *(const ulonglong2*)(q1p + d4 * 4);
            ffma2(acc0, kv.x, q0.x); ffma2(acc0, kv.y, q0.y);
            ffma2(acc1, kv.x, q1.x); ffma2(acc1, kv.y, q1.y);
        }
        S[il0][j] = hadd2(acc0) * scale + b0row[j];
        S[il1][j] = hadd2(acc1) * scale + b1row[j];
    }
    __syncwarp();

    // softmax (exp stored unnormalized, inv kept in regs)
    float inv0, inv1;
#pragma unroll
    for (int rr = 0; rr < 2; rr++) {
        float* Sr = (rr == 0) ? &S[il0][0] : &S[il1][0];
        float mx = -3.4e38f;
        for (int c = lane; c < NNx; c += 32) mx = fmaxf(mx, Sr[c]);
#pragma unroll
        for (int o = 16; o > 0; o >>= 1) mx = fmaxf(mx, __shfl_xor_sync(~0u, mx, o));
        float sum = 0.f;
        for (int c = lane; c < NNx; c += 32) {
            float e = __expf(Sr[c] - mx);
            Sr[c] = e;
            sum += e;
        }
#pragma unroll
        for (int o = 16; o > 0; o >>= 1) sum += __shfl_xor_sync(~0u, sum, o);
        if (rr == 0) inv0 = 1.0f / sum; else inv1 = 1.0f / sum;
    }
    __syncwarp();

    // AV: lane = (half, d-pair); half-warps split the j range
    int half = lane >> 4;
    int dp = (lane & 15) * 2;
    const float* vbase = g_vh + bhbase * DHx;
    float a00 = 0.f, a01 = 0.f, a10 = 0.f, a11 = 0.f;
    int jb = half * (NNx / 2);
    for (int jj = 0; jj < NNx / 2; jj += 4) {
        int j = jb + jj;
        float4 pA = *(const float4*)&S[il0][j];
        float4 pB = *(const float4*)&S[il1][j];
        const float* vp = vbase + (size_t)j * DHx + dp;
        float2 v0 = *(const float2*)(vp);
        float2 v1 = *(const float2*)(vp + 32);
        float2 v2 = *(const float2*)(vp + 64);
        float2 v3 = *(const float2*)(vp + 96);
        a00 += pA.x * v0.x + pA.y * v1.x + pA.z * v2.x + pA.w * v3.x;
        a01 += pA.x * v0.y + pA.y * v1.y + pA.z * v2.y + pA.w * v3.y;
        a10 += pB.x * v0.x + pB.y * v1.x + pB.z * v2.x + pB.w * v3.x;
        a11 += pB.x * v0.y + pB.y * v1.y + pB.z * v2.y + pB.w * v3.y;
    }
    a00 += __shfl_down_sync(~0u, a00, 16);
    a01 += __shfl_down_sync(~0u, a01, 16);
    a10 += __shfl_down_sync(~0u, a10, 16);
    a11 += __shfl_down_sync(~0u, a11, 16);

    if (half == 0) {
        size_t bnA = (size_t)b * NNx + iA;
        size_t bnB = (size_t)b * NNx + iB;
        float2 gA = *(const float2*)&g_qkvg[bnA * 2048 + 1536 + h * DHx + dp];
        float2 gB = *(const float2*)&g_qkvg[bnB * 2048 + 1536 + h * DHx + dp];
        float2 oA, oB;
        oA.x = a00 * inv0 * (1.0f / (1.0f + __expf(-gA.x)));
        oA.y = a01 * inv0 * (1.0f / (1.0f + __expf(-gA.y)));
        oB.x = a10 * inv1 * (1.0f / (1.0f + __expf(-gB.x)));
        oB.y = a11 * inv1 * (1.0f / (1.0f + __expf(-gB.y)));
        *(float2*)&g_og[bnA * INNERx + h * DHx + dp] = oA;
        *(float2*)&g_og[bnB * INNERx + h * DHx + dp] = oB;
    }
}

// ---------------- K6: output GEMM (f32x2, i-pair packed) ----------------
__global__ void k_gemm_out(const float* __restrict__ W, const float* __restrict__ bo,
                           float* __restrict__ C) {
    __shared__ __align__(16) float As[16][128];
    __shared__ __align__(16) float Bs[16][64];
    int bm = blockIdx.y * 128, bn = blockIdx.x * 64;
    int tid = threadIdx.x;
    int tr = tid >> 4, tc = tid & 15;
    u64 acc[4][4];
#pragma unroll
    for (int i = 0; i < 4; i++)
#pragma unroll
        for (int j = 0; j < 4; j++) acc[i][j] = 0ull;

    for (int k0 = 0; k0 < 512; k0 += 16) {
#pragma unroll
        for (int q = 0; q < 2; q++) {
            int f = tid * 2 + q;
            int r = f >> 2, c4 = (f & 3) << 2;
            float4 a = *(const float4*)&g_og[(size_t)(bm + r) * 512 + k0 + c4];
            As[c4 + 0][r] = a.x; As[c4 + 1][r] = a.y;
            As[c4 + 2][r] = a.z; As[c4 + 3][r] = a.w;
        }
        {
            int r = tid >> 4, c = (tid & 15) << 2;
            float4 bv = *(const float4*)&W[(size_t)(k0 + r) * 512 + bn + c];
            *(float4*)&Bs[r][c] = bv;
        }
        __syncthreads();
#pragma unroll
        for (int kk = 0; kk < 16; kk++) {
            ulonglong2 aLo = *(const ulonglong2*)&As[kk][tr * 8];
            ulonglong2 aHi = *(const ulonglong2*)&As[kk][tr * 8 + 4];
            float4 b0 = *(const float4*)&Bs[kk][tc * 4];
            u64 s0 = splat2(b0.x), s1 = splat2(b0.y), s2 = splat2(b0.z), s3 = splat2(b0.w);
            ffma2(acc[0][0], aLo.x, s0); ffma2(acc[0][1], aLo.x, s1);
            ffma2(acc[0][2], aLo.x, s2); ffma2(acc[0][3], aLo.x, s3);
            ffma2(acc[1][0], aLo.y, s0); ffma2(acc[1][1], aLo.y, s1);
            ffma2(acc[1][2], aLo.y, s2); ffma2(acc[1][3], aLo.y, s3);
            ffma2(acc[2][0], aHi.x, s0); ffma2(acc[2][1], aHi.x, s1);
            ffma2(acc[2][2], aHi.x, s2); ffma2(acc[2][3], aHi.x, s3);
            ffma2(acc[3][0], aHi.y, s0); ffma2(acc[3][1], aHi.y, s1);
            ffma2(acc[3][2], aHi.y, s2); ffma2(acc[3][3], aHi.y, s3);
        }
        __syncthreads();
    }
#pragma unroll
    for (int ip = 0; ip < 4; ip++) {
        int r0 = bm + tr * 8 + ip * 2;
#pragma unroll
        for (int j = 0; j < 4; j++) {
            int col = bn + tc * 4 + j;
            float2 v = up2(acc[ip][j]);
            C[(size_t)r0 * 512 + col]       = v.x + bo[col];
            C[(size_t)(r0 + 1) * 512 + col] = v.y + bo[col];
        }
    }
}

// ---------------- launch ----------------
extern "C" void kernel_launch(void* const* d_in, const int* in_sizes, int n_in,
                              void* d_out, int out_size) {
    const float* node = (const float*)d_in[0];
    const float* pair = (const float*)d_in[1];
    const int*   mask = (const int*)d_in[2];
    const float* nnw  = (const float*)d_in[3];
    const float* nnb  = (const float*)d_in[4];
    const float* qkvw = (const float*)d_in[5];
    const float* qkvb = (const float*)d_in[6];
    const float* gw   = (const float*)d_in[7];
    const float* gb   = (const float*)d_in[8];
    const float* qlw  = (const float*)d_in[9];
    const float* qlb  = (const float*)d_in[10];
    const float* klw  = (const float*)d_in[11];
    const float* klb  = (const float*)d_in[12];
    const float* pnw  = (const float*)d_in[13];
    const float* pnb  = (const float*)d_in[14];
    const float* bw   = (const float*)d_in[15];
    const float* ow   = (const float*)d_in[16];
    const float* ob   = (const float*)d_in[17];
    float* out = (float*)d_out;

    k_prep<<<1, 256>>>(bw, pnw, pnb);
    k_ln_node<<<BB * NNx, 256>>>(node, nnw, nnb);
    k_gemm_qkvg<<<dim3(2048 / 64, (BB * NNx) / 128), 256>>>(qkvw, qkvb, gw, gb);
    k_lnqk<<<BB * NNx, 256>>>(qlw, qlb, klw, klb);
    k_pairbias<<<dim3(NNx / 64, NNx, BB), 256>>>(pair, mask);
    k_attn<<<dim3(NNx / 12, HHx, BB), 192>>>();
    k_gemm_out<<<dim3(512 / 64, (BB * NNx) / 128), 256>>>(ow, ob, out);
}